// round 15
// baseline (speedup 1.0000x reference)
#include <cuda_runtime.h>
#include <math.h>
#include <stdint.h>

#define KNUM 1024
#define DNUM 64
#define NNUM 32768
#define TB   128            // threads per block = tokens per block
#define NBLK (NNUM / TB)    // 256
#define CH   128            // codes per smem chunk (64 pairs, 32 KB)
#define NPAIR (CH / 2)      // 64 pairs per chunk
#define NCHUNK (KNUM / CH)  // 8
#define HWB  6
#define DUAL_STEPS 10

// ---- device scratch ----
__device__ float g_cc[KNUM];
__device__ unsigned long long g_pk[KNUM / 2 * DNUM];  // packed codebook {c[2p][d], c[2p+1][d]}
__device__ float g_tgt[KNUM];       // normalized gaussian target
__device__ float g_ltg[KNUM];       // log(target)
__device__ int   g_hist[KNUM];      // zero at load; last CTA re-zeroes each replay
__device__ float g_msep[NBLK];
__device__ int   g_done;            // zero at load; last CTA resets

// packed f32x2 helpers (each lane is an independent IEEE-rn op == scalar fmaf)
__device__ __forceinline__ void fma2(unsigned long long& acc,
                                     unsigned long long a, unsigned long long b) {
    asm("fma.rn.f32x2 %0, %1, %2, %0;" : "+l"(acc) : "l"(a), "l"(b));
}
__device__ __forceinline__ unsigned long long dup2(float v) {
    unsigned long long r;
    asm("mov.b64 %0, {%1, %1};" : "=l"(r) : "f"(v));
    return r;
}
__device__ __forceinline__ void unpk(float& lo, float& hi, unsigned long long v) {
    asm("mov.b64 {%0, %1}, %2;" : "=f"(lo), "=f"(hi) : "l"(v));
}

// 128-thread block reduce (shuffle + 4-warp smem stage)
__device__ __forceinline__ float bred128(float v, volatile float* red4, int t) {
    #pragma unroll
    for (int off = 16; off > 0; off >>= 1)
        v += __shfl_down_sync(0xFFFFFFFFu, v, off);
    if ((t & 31) == 0) red4[t >> 5] = v;
    __syncthreads();
    float r = red4[0] + red4[1] + red4[2] + red4[3];
    __syncthreads();
    return r;
}

// ============================================================
// Kernel 0: blocks 0-7 = coalesced codebook prep (cc + pack);
//           block 8    = gaussian target / log-target.
// ============================================================
__global__ __launch_bounds__(128) void prep_kernel(const float* __restrict__ cb) {
    const int tid = threadIdx.x;

    if (blockIdx.x == 8) {
        __shared__ float red4[4];
        float tg[8];
        float s = 0.f;
        #pragma unroll
        for (int j = 0; j < 8; ++j) {
            int i = tid + 128 * j;
            float z = ((float)i - 511.5f) / (1024.0f / 6.0f);
            tg[j] = expf(-0.5f * z * z);
            s += tg[j];
        }
        float ts1 = bred128(s, red4, tid);
        s = 0.f;
        #pragma unroll
        for (int j = 0; j < 8; ++j) {
            tg[j] = tg[j] / fmaxf(ts1, 1e-12f);
            tg[j] = fmaxf(tg[j], 1e-12f);
            s += tg[j];
        }
        float ts2 = bred128(s, red4, tid);
        #pragma unroll
        for (int j = 0; j < 8; ++j) {
            int i = tid + 128 * j;
            float tv = tg[j] / ts2;
            g_tgt[i] = tv;
            g_ltg[i] = logf(fmaxf(tv, 1e-12f));
        }
        return;
    }

    __shared__ float scb[CH * DNUM];            // 32 KB
    const int k0 = blockIdx.x * CH;

    { // coalesced load: 2048 uint4
        const uint4* src = (const uint4*)(cb + (size_t)k0 * DNUM);
        uint4*       dst = (uint4*)scb;
        #pragma unroll
        for (int i = 0; i < (CH * DNUM / 4) / 128; ++i)
            dst[tid + i * 128] = src[tid + i * 128];
    }
    __syncthreads();

    { // cc: thread = code, bit-exact sequential fmaf chain
        const float* r = scb + tid * DNUM;
        float s = 0.f;
        #pragma unroll
        for (int d = 0; d < DNUM; ++d) s = fmaf(r[d], r[d], s);
        g_cc[k0 + tid] = s;
    }

    { // pack: pairwise over codes, coalesced 8B writes
        unsigned long long* dst = g_pk + (size_t)(k0 / 2) * DNUM;
        #pragma unroll
        for (int i = tid; i < NPAIR * DNUM; i += 128) {
            int p = i >> 6, d = i & 63;
            dst[i] = (unsigned long long)__float_as_uint(scb[(2 * p) * DNUM + d]) |
                     ((unsigned long long)__float_as_uint(scb[(2 * p + 1) * DNUM + d]) << 32);
        }
    }
}

// ============================================================
// Kernel 1: per-token argmin (proven bit-exact sequence) with
// the OT/loss/perplexity epilogue folded into the LAST CTA.
// ============================================================
__global__ __launch_bounds__(TB, 2) void assign_kernel(const float* __restrict__ x,
                                                       const float* __restrict__ cb,
                                                       float* __restrict__ out) {
    __shared__ unsigned long long spk[2][NPAIR * DNUM];  // 2 x 32 KB (reused by finalize)
    __shared__ float sccs[KNUM];                          // 4 KB
    __shared__ float sred[TB];
    __shared__ int   s_last;

    const int tid = threadIdx.x;
    const int n   = blockIdx.x * TB + tid;
    const int b   = n >> 10;
    const int hw  = n & 1023;
    const float* xp = x + (size_t)b * (DNUM * 1024) + hw;

    auto load_chunk = [&](int c, unsigned long long* buf) {
        const uint4* src = (const uint4*)(g_pk + (size_t)(c * NPAIR) * DNUM);
        uint4*       dst = (uint4*)buf;
        #pragma unroll
        for (int i = 0; i < 16; ++i)
            dst[tid + i * TB] = src[tid + i * TB];
    };

    load_chunk(0, spk[0]);

    #pragma unroll
    for (int i = tid; i < KNUM; i += TB) sccs[i] = g_cc[i];

    // ---- load x, bit-exact xxr tree, duplicated f32x2 x regs
    float xf[DNUM];
    #pragma unroll
    for (int c = 0; c < DNUM; ++c) xf[c] = xp[(size_t)c * 1024];

    float p[32];
    #pragma unroll
    for (int l = 0; l < 32; ++l)
        p[l] = __fadd_rn(__fmul_rn(xf[l], xf[l]), __fmul_rn(xf[l + 32], xf[l + 32]));
    #pragma unroll
    for (int off = 16; off > 0; off >>= 1)
        #pragma unroll
        for (int l = 0; l < 16; ++l)
            if (l < off) p[l] = __fadd_rn(p[l], p[l + off]);
    const float xxr = p[0];

    unsigned long long xd[DNUM];
    #pragma unroll
    for (int d = 0; d < DNUM; ++d) xd[d] = dup2(xf[d]);

    float best = INFINITY;
    int   bidx = 0;

    __syncthreads();                            // chunk 0 + sccs ready

    for (int c = 0; c < NCHUNK; ++c) {
        const unsigned long long* cur = spk[c & 1];
        if (c + 1 < NCHUNK) load_chunk(c + 1, spk[(c + 1) & 1]);

        for (int pp = 0; pp < NPAIR; ++pp) {
            const ulonglong2* cp = (const ulonglong2*)(cur + pp * DNUM);
            unsigned long long a0 = 0ull, a1 = 0ull, a2 = 0ull, a3 = 0ull;
            #pragma unroll
            for (int c4 = 0; c4 < 16; ++c4) {
                ulonglong2 v01 = cp[2 * c4];
                ulonglong2 v23 = cp[2 * c4 + 1];
                fma2(a0, xd[4 * c4 + 0], v01.x);
                fma2(a1, xd[4 * c4 + 1], v01.y);
                fma2(a2, xd[4 * c4 + 2], v23.x);
                fma2(a3, xd[4 * c4 + 3], v23.y);
            }
            float a0l, a0h, a1l, a1h, a2l, a2h, a3l, a3h;
            unpk(a0l, a0h, a0); unpk(a1l, a1h, a1);
            unpk(a2l, a2h, a2); unpk(a3l, a3h, a3);

            const int j0 = c * CH + 2 * pp;
            { // code j0 (exact reference assembly)
                float t  = __fadd_rn(__fadd_rn(a0l, a1l), __fadd_rn(a2l, a3l));
                float u  = __fadd_rn(xxr, sccs[j0]);
                float dk = __fadd_rn(u, __fmul_rn(-2.f, t));
                if (dk < best) { best = dk; bidx = j0; }
            }
            { // code j0+1 (after j0 => ascending first-index preserved)
                float t  = __fadd_rn(__fadd_rn(a0h, a1h), __fadd_rn(a2h, a3h));
                float u  = __fadd_rn(xxr, sccs[j0 + 1]);
                float dk = __fadd_rn(u, __fmul_rn(-2.f, t));
                if (dk < best) { best = dk; bidx = j0 + 1; }
            }
        }
        __syncthreads();
    }

    atomicAdd(&g_hist[bidx], 1);

    // quantized output (= chosen codeword) in [B,C,H,W] layout + MSE
    const float* cw = cb + (size_t)bidx * DNUM;
    float*       op = out + (size_t)b * (DNUM * 1024) + hw;
    float mse = 0.f;
    #pragma unroll
    for (int c = 0; c < DNUM; ++c) {
        float cv = cw[c];
        op[(size_t)c * 1024] = cv;
        float dd = cv - xf[c];
        mse = fmaf(dd, dd, mse);
    }

    sred[tid] = mse;
    __syncthreads();
    for (int s = TB / 2; s > 0; s >>= 1) {
        if (tid < s) sred[tid] += sred[tid + s];
        __syncthreads();
    }
    if (tid == 0) g_msep[blockIdx.x] = sred[0];
    __syncthreads();

    // ======== last-CTA detection (canonical fence + counter) ========
    if (tid == 0) {
        __threadfence();
        int d = atomicAdd(&g_done, 1);
        s_last = (d == NBLK - 1);
    }
    __syncthreads();
    if (!s_last) return;
    if (tid == 0) g_done = 0;                   // reset for next graph replay

    // ======== inline finalize: 128 threads, 8 support points each ========
    float* s_src = (float*)spk;                 // reuse dead chunk smem
    float* s_lse = ((float*)spk) + KNUM;

    float hist[8], sr[8], tgt[8], ltg[8], phi[8];
    {
        float es = 0.f;
        #pragma unroll
        for (int j = 0; j < 8; ++j) {
            int i = tid + 128 * j;
            int hraw = g_hist[i];
            g_hist[i] = 0;                      // reset for next replay
            hist[j] = (float)hraw * (1.0f / 32768.0f);
            es += hist[j] * logf(hist[j] + 1e-10f);
        }
        float esum = bred128(es, sred, tid);
        float perp = expf(-esum);

        float s1 = 0.f;
        #pragma unroll
        for (int j = 0; j < 8; ++j) { sr[j] = fmaxf(hist[j], 1e-12f); s1 += sr[j]; }
        float ss1 = bred128(s1, sred, tid);
        float s2 = 0.f;
        #pragma unroll
        for (int j = 0; j < 8; ++j) {
            sr[j] = sr[j] / ss1;
            sr[j] = fmaxf(sr[j], 1e-12f);
            s2 += sr[j];
        }
        float ss2 = bred128(s2, sred, tid);
        #pragma unroll
        for (int j = 0; j < 8; ++j) {
            int i = tid + 128 * j;
            sr[j] = sr[j] / ss2;
            s_src[i] = sr[j];
            tgt[j] = g_tgt[i];
            ltg[j] = g_ltg[i];
            phi[j] = 0.f;
        }
        __syncthreads();

        for (int step = 0; step < DUAL_STEPS; ++step) {
            #pragma unroll
            for (int j = 0; j < 8; ++j) {
                int i = tid + 128 * j;
                s_lse[i] = __fadd_rn(ltg[j], __fmul_rn(phi[j], 20.0f));
            }
            __syncthreads();
            #pragma unroll
            for (int j = 0; j < 8; ++j) {
                int i = tid + 128 * j;
                int lo = (i - HWB < 0) ? 0 : i - HWB;
                int hi = (i + HWB > KNUM - 1) ? KNUM - 1 : i + HWB;
                float cs = 0.f;
                for (int q = lo; q <= hi; ++q) {
                    float c = fabsf((float)(i - q));
                    float a = __fadd_rn(ltg[j], __fmul_rn(__fadd_rn(-c, phi[j]), 20.0f));
                    cs = fmaf(s_src[q], __expf(a - s_lse[q]), cs);
                }
                phi[j] = phi[j] + 0.5f * (tgt[j] - cs);
            }
            __syncthreads();
        }

        float os = 0.f;
        #pragma unroll
        for (int j = 0; j < 8; ++j) {
            float lse_j = __fadd_rn(ltg[j], __fmul_rn(phi[j], 20.0f));
            os += sr[j] * (-0.05f * lse_j) + tgt[j] * phi[j];
        }
        float ot = bred128(os, sred, tid);

        float mp = g_msep[tid] + g_msep[tid + 128];
        float msum = bred128(mp, sred, tid);
        float msef = msum * (1.0f / 2097152.0f);

        if (tid == 0) {
            float loss = msef + 0.25f * msef + 1.0f * ot;
            out[2097152] = loss;
            out[2097153] = perp;
        }
    }
}

// ============================================================
extern "C" void kernel_launch(void* const* d_in, const int* in_sizes, int n_in,
                              void* d_out, int out_size) {
    const float* x  = (const float*)d_in[0];
    const float* cb = (const float*)d_in[1];
    float* out = (float*)d_out;
    (void)in_sizes; (void)n_in; (void)out_size;

    prep_kernel<<<9, 128>>>(cb);
    assign_kernel<<<NBLK, TB>>>(x, cb, out);
}

// round 16
// speedup vs baseline: 1.1056x; 1.1056x over previous
#include <cuda_runtime.h>
#include <math.h>
#include <stdint.h>

#define KNUM 1024
#define DNUM 64
#define NNUM 32768
#define TB   128            // threads per CTA = tokens per group
#define NGRP 256            // token groups
#define QSPL 4              // codebook quarters
#define CODES_Q 256         // codes per quarter
#define CH   128            // codes per smem chunk (64 pairs, 32 KB)
#define NPAIR (CH / 2)
#define HWB  6
#define DUAL_STEPS 10

// ---- device scratch ----
__device__ float g_cc[KNUM];
__device__ unsigned long long g_pk[KNUM / 2 * DNUM];  // packed codebook {c[2p][d], c[2p+1][d]}
__device__ float g_tgt[KNUM];
__device__ float g_ltg[KNUM];
__device__ unsigned long long g_part[QSPL * NNUM];    // per-quarter (dk, idx) partials
__device__ int   g_grp[NGRP];       // zero at load; last arriver resets
__device__ int   g_hist[KNUM];      // zero at load; finalize re-zeroes
__device__ float g_msep[NGRP];

// packed f32x2 helpers (each lane = independent IEEE-rn op == scalar fmaf)
__device__ __forceinline__ void fma2(unsigned long long& acc,
                                     unsigned long long a, unsigned long long b) {
    asm("fma.rn.f32x2 %0, %1, %2, %0;" : "+l"(acc) : "l"(a), "l"(b));
}
__device__ __forceinline__ unsigned long long dup2(float v) {
    unsigned long long r;
    asm("mov.b64 %0, {%1, %1};" : "=l"(r) : "f"(v));
    return r;
}
__device__ __forceinline__ void unpk(float& lo, float& hi, unsigned long long v) {
    asm("mov.b64 {%0, %1}, %2;" : "=f"(lo), "=f"(hi) : "l"(v));
}

__device__ __forceinline__ float bred128(float v, volatile float* red4, int t) {
    #pragma unroll
    for (int off = 16; off > 0; off >>= 1)
        v += __shfl_down_sync(0xFFFFFFFFu, v, off);
    if ((t & 31) == 0) red4[t >> 5] = v;
    __syncthreads();
    float r = red4[0] + red4[1] + red4[2] + red4[3];
    __syncthreads();
    return r;
}

// ============================================================
// Kernel 0: blocks 0-7 codebook prep (cc + pack); block 8 target.
// ============================================================
__global__ __launch_bounds__(128) void prep_kernel(const float* __restrict__ cb) {
    const int tid = threadIdx.x;

    if (blockIdx.x == 8) {
        __shared__ float red4[4];
        float tg[8];
        float s = 0.f;
        #pragma unroll
        for (int j = 0; j < 8; ++j) {
            int i = tid + 128 * j;
            float z = ((float)i - 511.5f) / (1024.0f / 6.0f);
            tg[j] = expf(-0.5f * z * z);
            s += tg[j];
        }
        float ts1 = bred128(s, red4, tid);
        s = 0.f;
        #pragma unroll
        for (int j = 0; j < 8; ++j) {
            tg[j] = tg[j] / fmaxf(ts1, 1e-12f);
            tg[j] = fmaxf(tg[j], 1e-12f);
            s += tg[j];
        }
        float ts2 = bred128(s, red4, tid);
        #pragma unroll
        for (int j = 0; j < 8; ++j) {
            int i = tid + 128 * j;
            float tv = tg[j] / ts2;
            g_tgt[i] = tv;
            g_ltg[i] = logf(fmaxf(tv, 1e-12f));
        }
        return;
    }

    __shared__ float scb[CH * DNUM];            // 32 KB
    const int k0 = blockIdx.x * CH;

    {
        const uint4* src = (const uint4*)(cb + (size_t)k0 * DNUM);
        uint4*       dst = (uint4*)scb;
        #pragma unroll
        for (int i = 0; i < (CH * DNUM / 4) / 128; ++i)
            dst[tid + i * 128] = src[tid + i * 128];
    }
    __syncthreads();

    { // cc: bit-exact sequential fmaf chain
        const float* r = scb + tid * DNUM;
        float s = 0.f;
        #pragma unroll
        for (int d = 0; d < DNUM; ++d) s = fmaf(r[d], r[d], s);
        g_cc[k0 + tid] = s;
    }

    { // pairwise pack, coalesced 8B writes
        unsigned long long* dst = g_pk + (size_t)(k0 / 2) * DNUM;
        #pragma unroll
        for (int i = tid; i < NPAIR * DNUM; i += 128) {
            int p = i >> 6, d = i & 63;
            dst[i] = (unsigned long long)__float_as_uint(scb[(2 * p) * DNUM + d]) |
                     ((unsigned long long)__float_as_uint(scb[(2 * p + 1) * DNUM + d]) << 32);
        }
    }
}

// ============================================================
// Kernel 1: K-split-4 argmin. grid = 1024: g = bid>>2, q = bid&3.
// Each CTA scans codes [q*256,(q+1)*256) with the PROVEN bit-exact
// sequence; last-of-group merges partials (first-index preserved).
// ============================================================
__global__ __launch_bounds__(TB, 3) void assign_kernel(const float* __restrict__ x,
                                                       const float* __restrict__ cb,
                                                       float* __restrict__ out) {
    __shared__ unsigned long long spk[NPAIR * DNUM];   // 32 KB chunk
    __shared__ float sccq[CODES_Q];                    // this quarter's cc
    __shared__ float sred[TB];
    __shared__ int   s_last;

    const int tid = threadIdx.x;
    const int g   = blockIdx.x >> 2;
    const int q   = blockIdx.x & 3;
    const int n   = g * TB + tid;
    const int b   = n >> 10;
    const int hw  = n & 1023;
    const float* xp = x + (size_t)b * (DNUM * 1024) + hw;

    #pragma unroll
    for (int i = tid; i < CODES_Q; i += TB) sccq[i] = g_cc[q * CODES_Q + i];

    // ---- load x, bit-exact xxr tree, duplicated f32x2 x regs
    float xf[DNUM];
    #pragma unroll
    for (int c = 0; c < DNUM; ++c) xf[c] = xp[(size_t)c * 1024];

    float p[32];
    #pragma unroll
    for (int l = 0; l < 32; ++l)
        p[l] = __fadd_rn(__fmul_rn(xf[l], xf[l]), __fmul_rn(xf[l + 32], xf[l + 32]));
    #pragma unroll
    for (int off = 16; off > 0; off >>= 1)
        #pragma unroll
        for (int l = 0; l < 16; ++l)
            if (l < off) p[l] = __fadd_rn(p[l], p[l + off]);
    const float xxr = p[0];

    unsigned long long xd[DNUM];
    #pragma unroll
    for (int d = 0; d < DNUM; ++d) xd[d] = dup2(xf[d]);

    float best = INFINITY;
    int   bidx = 0;

    for (int c = 0; c < CODES_Q / CH; ++c) {           // 2 chunks
        __syncthreads();
        {
            const int cg = q * (CODES_Q / CH) + c;     // global chunk id
            const uint4* src = (const uint4*)(g_pk + (size_t)(cg * NPAIR) * DNUM);
            uint4*       dst = (uint4*)spk;
            #pragma unroll
            for (int i = 0; i < 16; ++i)
                dst[tid + i * TB] = src[tid + i * TB];
        }
        __syncthreads();

        for (int pp = 0; pp < NPAIR; ++pp) {
            const ulonglong2* cp = (const ulonglong2*)(spk + pp * DNUM);
            unsigned long long a0 = 0ull, a1 = 0ull, a2 = 0ull, a3 = 0ull;
            #pragma unroll
            for (int c4 = 0; c4 < 16; ++c4) {
                ulonglong2 v01 = cp[2 * c4];
                ulonglong2 v23 = cp[2 * c4 + 1];
                fma2(a0, xd[4 * c4 + 0], v01.x);
                fma2(a1, xd[4 * c4 + 1], v01.y);
                fma2(a2, xd[4 * c4 + 2], v23.x);
                fma2(a3, xd[4 * c4 + 3], v23.y);
            }
            float a0l, a0h, a1l, a1h, a2l, a2h, a3l, a3h;
            unpk(a0l, a0h, a0); unpk(a1l, a1h, a1);
            unpk(a2l, a2h, a2); unpk(a3l, a3h, a3);

            const int jl = c * CH + 2 * pp;            // quarter-local code id
            { // exact reference assembly, code q*256+jl
                float t  = __fadd_rn(__fadd_rn(a0l, a1l), __fadd_rn(a2l, a3l));
                float u  = __fadd_rn(xxr, sccq[jl]);
                float dk = __fadd_rn(u, __fmul_rn(-2.f, t));
                if (dk < best) { best = dk; bidx = q * CODES_Q + jl; }
            }
            {
                float t  = __fadd_rn(__fadd_rn(a0h, a1h), __fadd_rn(a2h, a3h));
                float u  = __fadd_rn(xxr, sccq[jl + 1]);
                float dk = __fadd_rn(u, __fmul_rn(-2.f, t));
                if (dk < best) { best = dk; bidx = q * CODES_Q + jl + 1; }
            }
        }
    }

    // publish this quarter's partial (plain store; no init needed)
    g_part[(size_t)q * NNUM + n] =
        ((unsigned long long)__float_as_uint(best) << 32) | (unsigned int)bidx;
    __threadfence();
    __syncthreads();
    if (tid == 0) {
        int d = atomicAdd(&g_grp[g], 1);
        s_last = (d == QSPL - 1);
    }
    __syncthreads();
    if (!s_last) return;
    if (tid == 0) g_grp[g] = 0;                        // reset for next replay
    __threadfence();                                   // acquire side

    // ---- merge 4 partials in q order: (dk, idx) lexicographic min
    float bd = INFINITY;
    int   bi = KNUM;
    #pragma unroll
    for (int qq = 0; qq < QSPL; ++qq) {
        unsigned long long v = g_part[(size_t)qq * NNUM + n];
        float dk = __uint_as_float((unsigned int)(v >> 32));
        int   ix = (int)(v & 0xFFFFFFFFu);
        if (dk < bd || (dk == bd && ix < bi)) { bd = dk; bi = ix; }
    }

    atomicAdd(&g_hist[bi], 1);

    // quantized output (= chosen codeword) + MSE (own xf is bit-same)
    const float* cw = cb + (size_t)bi * DNUM;
    float*       op = out + (size_t)b * (DNUM * 1024) + hw;
    float mse = 0.f;
    #pragma unroll
    for (int c = 0; c < DNUM; ++c) {
        float cv = cw[c];
        op[(size_t)c * 1024] = cv;
        float dd = cv - xf[c];
        mse = fmaf(dd, dd, mse);
    }

    sred[tid] = mse;
    __syncthreads();
    for (int s = TB / 2; s > 0; s >>= 1) {
        if (tid < s) sred[tid] += sred[tid + s];
        __syncthreads();
    }
    if (tid == 0) g_msep[g] = sred[0];
}

// ============================================================
// Kernel 2 (R14 proven): perplexity, OT dual ascent, loss.
// ============================================================
__device__ __forceinline__ float bred(float v, float* red32, int t) {
    #pragma unroll
    for (int off = 16; off > 0; off >>= 1)
        v += __shfl_down_sync(0xFFFFFFFFu, v, off);
    const int w = t >> 5, lane = t & 31;
    if (lane == 0) red32[w] = v;
    __syncthreads();
    if (w == 0) {
        float s = red32[lane];
        #pragma unroll
        for (int off = 16; off > 0; off >>= 1)
            s += __shfl_down_sync(0xFFFFFFFFu, s, off);
        if (lane == 0) red32[0] = s;
    }
    __syncthreads();
    float r = red32[0];
    __syncthreads();
    return r;
}

__global__ __launch_bounds__(1024) void finalize_kernel(float* __restrict__ out) {
    __shared__ float s_src[KNUM], s_lse[KNUM];
    __shared__ float red32[32];
    const int t = threadIdx.x;

    const int hraw = g_hist[t];
    g_hist[t] = 0;
    const float hist = (float)hraw * (1.0f / 32768.0f);

    float ent  = hist * logf(hist + 1e-10f);
    float esum = bred(ent, red32, t);
    float perp = expf(-esum);

    float sr  = fmaxf(hist, 1e-12f);
    float ss1 = bred(sr, red32, t);
    sr = sr / ss1;
    sr = fmaxf(sr, 1e-12f);
    float ss2 = bred(sr, red32, t);
    sr = sr / ss2;
    s_src[t] = sr;

    const float tgt_t = g_tgt[t];
    const float ltg_t = g_ltg[t];
    __syncthreads();

    const int lo = (t - HWB < 0) ? 0 : t - HWB;
    const int hi = (t + HWB > KNUM - 1) ? KNUM - 1 : t + HWB;

    float phi_t = 0.f;
    for (int step = 0; step < DUAL_STEPS; ++step) {
        s_lse[t] = __fadd_rn(ltg_t, __fmul_rn(phi_t, 20.0f));
        __syncthreads();
        float cs = 0.f;
        for (int i = lo; i <= hi; ++i) {
            float c = fabsf((float)(i - t));
            float a = __fadd_rn(ltg_t, __fmul_rn(__fadd_rn(-c, phi_t), 20.0f));
            cs = fmaf(s_src[i], __expf(a - s_lse[i]), cs);
        }
        __syncthreads();
        phi_t = phi_t + 0.5f * (tgt_t - cs);
    }

    float lse_t = __fadd_rn(ltg_t, __fmul_rn(phi_t, 20.0f));
    float obj = sr * (-0.05f * lse_t) + tgt_t * phi_t;
    float ot  = bred(obj, red32, t);

    float mp   = (t < NGRP) ? g_msep[t] : 0.f;
    float msum = bred(mp, red32, t);
    float mse  = msum * (1.0f / 2097152.0f);

    if (t == 0) {
        float loss = mse + 0.25f * mse + 1.0f * ot;
        out[2097152] = loss;
        out[2097153] = perp;
    }
}

// ============================================================
extern "C" void kernel_launch(void* const* d_in, const int* in_sizes, int n_in,
                              void* d_out, int out_size) {
    const float* x  = (const float*)d_in[0];
    const float* cb = (const float*)d_in[1];
    float* out = (float*)d_out;
    (void)in_sizes; (void)n_in; (void)out_size;

    prep_kernel<<<9, 128>>>(cb);
    assign_kernel<<<NGRP * QSPL, TB>>>(x, cb, out);
    finalize_kernel<<<1, 1024>>>(out);
}